// round 9
// baseline (speedup 1.0000x reference)
#include <cuda_runtime.h>
#include <math.h>

#define NTHREADS 256
#define NW 8            // warps per block = probes per round
#define NCLS 1000
#define NPAD 1024
#define NT 800
#define TSTEP 0.00125f
#define TOL 0.01f

__device__ __forceinline__ float ex2(float x) {
    float y;
    asm("ex2.approx.f32 %0, %1;" : "=f"(y) : "f"(x));
    return y;
}

__global__ __launch_bounds__(NTHREADS)
void logit_compression_kernel(const float* __restrict__ logits,
                              float* __restrict__ out) {
    __shared__ float dsm[NPAD];      // d_j = fl(l_j - m), padded with -inf
    __shared__ float redm[NW];
    __shared__ float red1[NW];
    __shared__ float ctbuf[2][NW];
    __shared__ float sbuf[2][NW];

    const int tid  = threadIdx.x;
    const int lane = tid & 31;
    const int w    = tid >> 5;
    const int row  = blockIdx.x;
    const float* lrow = logits + row * NCLS;
    float* orow = out + row * NCLS;

    // ---- load row ----
    float r[4];
#pragma unroll
    for (int k = 0; k < 4; k++) {
        int idx = tid + k * NTHREADS;
        r[k] = (idx < NCLS) ? lrow[idx] : -INFINITY;
    }

    // ---- block max ----
    float mv = fmaxf(fmaxf(r[0], r[1]), fmaxf(r[2], r[3]));
#pragma unroll
    for (int o = 16; o > 0; o >>= 1) mv = fmaxf(mv, __shfl_xor_sync(0xffffffffu, mv, o));
    if (lane == 0) redm[w] = mv;
    __syncthreads();
    float m = redm[0];
#pragma unroll
    for (int i = 1; i < NW; i++) m = fmaxf(m, redm[i]);

    // ---- d -> smem; S1 with ACCURATE expf (decision-critical for conf) ----
    float s1 = 0.0f;
#pragma unroll
    for (int k = 0; k < 4; k++) {
        float dk = __fsub_rn(r[k], m);     // -inf for padding lanes
        dsm[tid + k * NTHREADS] = dk;
        s1 += expf(dk);                    // expf(-inf) == 0
    }
#pragma unroll
    for (int o = 16; o > 0; o >>= 1) s1 += __shfl_xor_sync(0xffffffffu, s1, o);
    if (lane == 0) red1[w] = s1;
    __syncthreads();                       // publishes red1 AND dsm
    const float S1 = ((red1[0] + red1[1]) + (red1[2] + red1[3]))
                   + ((red1[4] + red1[5]) + (red1[6] + red1[7]));

    // ---- conf, bin, target confidence (reference rounding) ----
    const float conf = __fdiv_rn(1.0f, S1);
    int b = (conf >= (2.0f / 3.0f)) ? 2 : (conf >= (1.0f / 3.0f)) ? 1 : 0;
    const float BL  = (b == 0) ? 0.0f : (b == 1) ? (1.0f / 3.0f) : (2.0f / 3.0f);
    const float NBL = (b == 0) ? 0.8f : (b == 1) ? 0.86666666666f : 0.93333333333f;
    const float nc  = __fadd_rn(NBL,
                     __fmul_rn((float)(1.0 / 15.0),
                               __fdiv_rn(__fsub_rn(conf, BL), 0.2666666667f)));
    const float Sthr = __fdiv_rn(1.0f, __fsub_rn(nc, TOL));   // guidance only

    // ---- search for first j with ct(j) >= nc - TOL, ct = 1/S(u_j), monotone.
    // Round 0: structural table (nc >= 0.8 => late crossings for soft rows).
    // Round >=1: if a bracket (p_lo,S_lo)-(hi,S_hi) exists, secant-interp on
    // log(S-1) vs u = 1/t, probe 8 CONSECUTIVE indices around the prediction
    // (adjacent fail/pass terminates); else uniform stride (proven fallback).
    const float4* d4 = (const float4*)dsm;
    const int P0[NW] = {480, 600, 672, 720, 752, 776, 792, 799};  // ascending

    int lo = 0, hi = NT;
    float ct_hi = 0.0f;        // ct at hi (valid when hi < NT)
    float s_hi = 0.0f;         // S at hi
    int   p_lo = -1;           // last known-false position
    float s_lo = 0.0f;         // S at p_lo
    bool  havebr = false;      // bracket valid
    int par = 0, iter = 0;

    while (lo < hi) {
        const int stride = (hi - lo + NW - 1) >> 3;
        const bool tab = (iter == 0);
        const bool itp = (!tab && havebr);

        int q = 0;
        if (itp) {
            // secant on y(u) = log(S-1); all threads compute identically.
            float u1 = __frcp_rn(__fsub_rn(1.0f, __fmul_rn(TSTEP, (float)p_lo)));
            float u2 = __frcp_rn(__fsub_rn(1.0f, __fmul_rn(TSTEP, (float)hi)));
            float y1 = __logf(s_lo - 1.0f);
            float y2 = __logf(s_hi - 1.0f);
            float yt = __logf(Sthr - 1.0f);
            float fr = (y1 - yt) / (y1 - y2);
            float jp;
            if (isfinite(fr) && fr >= 0.0f && fr <= 1.5f) {
                float us = u1 + fr * (u2 - u1);
                jp = (1.0f - __frcp_rn(us)) * 800.0f;
            } else {
                jp = 0.5f * (float)(lo + hi);
            }
            int jpi = (int)ceilf(jp) - 2;
            int qmax = hi - NW;              // q+7 <= hi-1 when possible
            if (qmax < lo) qmax = lo;
            q = (jpi < lo) ? lo : ((jpi > qmax) ? qmax : jpi);
        }

        int pos; bool active;
        if (tab)      { pos = P0[w];           active = true; }
        else if (itp) { pos = q + w;           active = (pos < hi); }
        else          { pos = lo + w * stride; active = (pos < hi); }

        float ctv = 0.0f, sv = 0.0f;
        if (active) {                          // warp-uniform branch
            float t    = __fsub_rn(1.0f, __fmul_rn(TSTEP, (float)pos));
            float invt = __frcp_rn(t);
            float c2   = __fmul_rn(invt, 1.4426950408889634f);
            float a0 = 0.0f, a1 = 0.0f, a2 = 0.0f, a3 = 0.0f;
#pragma unroll
            for (int k = 0; k < 8; k++) {
                float4 v = d4[lane + k * 32];
                a0 += ex2(__fmul_rn(v.x, c2));
                a1 += ex2(__fmul_rn(v.y, c2));
                a2 += ex2(__fmul_rn(v.z, c2));
                a3 += ex2(__fmul_rn(v.w, c2));
            }
            float s = (a0 + a1) + (a2 + a3);
#pragma unroll
            for (int o = 16; o > 0; o >>= 1) s += __shfl_xor_sync(0xffffffffu, s, o);
            sv  = s;
            ctv = __frcp_rn(s);                // ct = 1/S
        }
        if (lane == 0) { ctbuf[par][w] = ctv; sbuf[par][w] = sv; }
        __syncthreads();   // single barrier per round (double-buffered)

        // Deterministic redundant interval update.
        int first = -1, previ = -1, lasti = -1;
        int pprev = 0, pfirst = 0, plast = 0;
#pragma unroll
        for (int i = 0; i < NW; i++) {
            int p  = tab ? P0[i] : (itp ? (q + i) : (lo + i * stride));
            bool a = tab ? true  : (p < hi);
            if (a) {
                if (first < 0) {
                    if (__fsub_rn(ctbuf[par][i], nc) >= -TOL) { first = i; pfirst = p; }
                    else { previ = i; pprev = p; }
                }
                lasti = i; plast = p;
            }
        }
        if (first >= 0) {
            ct_hi = ctbuf[par][first];
            s_hi  = sbuf[par][first];
            hi = pfirst;
            if (previ >= 0) {
                p_lo = pprev; s_lo = sbuf[par][previ];
                lo = pprev + 1;
            }
            havebr = (p_lo >= 0);
        } else {
            p_lo = plast; s_lo = sbuf[par][lasti];
            lo = plast + 1;
            havebr = (hi < NT);
        }
        par ^= 1;
        iter++;
    }

    // ---- band check + output ----
    bool found = false;
    float tj = 1.0f;
    if (hi < NT) {
        float g = __fsub_rn(ct_hi, nc);      // >= -TOL by construction
        found = (fabsf(g) <= TOL);
        tj = __fsub_rn(1.0f, __fmul_rn(TSTEP, (float)hi));
    }
#pragma unroll
    for (int k = 0; k < 4; k++) {
        int idx = tid + k * NTHREADS;
        if (idx < NCLS) orow[idx] = found ? __fdiv_rn(r[k], tj) : r[k];
    }
}

extern "C" void kernel_launch(void* const* d_in, const int* in_sizes, int n_in,
                              void* d_out, int out_size) {
    const float* logits = (const float*)d_in[0];
    float* out = (float*)d_out;
    int B = in_sizes[0] / NCLS;   // 128 rows
    logit_compression_kernel<<<B, NTHREADS>>>(logits, out);
}